// round 1
// baseline (speedup 1.0000x reference)
#include <cuda_runtime.h>
#include <cuda_bf16.h>
#include <mma.h>
#include <cstdint>

using namespace nvcuda;

// Problem constants (fixed dataset)
constexpr int AEVD = 384;
constexpr int H1D  = 160;
constexpr int H2D  = 128;
constexpr int H3D  = 96;
constexpr int MTILE = 128;   // atoms per CTA
constexpr int KC    = 32;    // K chunk for staging

// SMEM layout (floats), all leading dims multiples of 4 (wmma ldm requirement)
constexpr int LDA_CH = KC + 4;          // 36
constexpr int LDH1   = H1D + 4;         // 164
constexpr int LDH2   = H2D + 4;         // 132
constexpr int LDH3   = 100;             // 96 + 4
constexpr int SZ_A   = MTILE * LDA_CH;  // 4608
constexpr int SZ_W   = KC * (H1D + 4);  // 5248 (max-N weight chunk)
constexpr int SZ_H1  = MTILE * LDH1;    // 20992 (also reused for h3)
constexpr int SZ_H2  = MTILE * LDH2;    // 16896
constexpr int SMEM_FLOATS = SZ_A + SZ_W + SZ_H1 + SZ_H2;  // 47744
constexpr int SMEM_BYTES  = SMEM_FLOATS * 4;              // 190976 B

__device__ float g_partials[4096];

__device__ __forceinline__ float celu_f(float x) {
    // celu(x, 0.1) = x>0 ? x : 0.1*(exp(x/0.1)-1)
    return x > 0.0f ? x : 0.1f * (expf(x * 10.0f) - 1.0f);
}

// One MLP layer: Out[128 x N] = celu(A[128 x K] @ W[K x N] + b)
// GATHER=true: A comes from global aev via sidx (rows gathered per K-chunk into sA).
// GATHER=false: A resident in shared memory (Asm, lda).
template<int K, int N, bool GATHER>
__device__ __forceinline__ void run_layer(
    const float* __restrict__ Ag,        // aev base (GATHER only)
    const int*   __restrict__ sidx,      // row -> atom (-1 = pad), smem
    const float* __restrict__ Asm, int lda,
    const float* __restrict__ Wg,        // K x N row-major, species base
    const float* __restrict__ bg,        // N
    float* sA, float* sW,
    float* Hout, int ldo)
{
    constexpr int TN = N / 16;
    constexpr int LW = N + 4;
    const int tid  = threadIdx.x;
    const int warp = tid >> 5;           // 0..7, m-tile = warp

    wmma::fragment<wmma::accumulator, 16, 16, 8, float> c[TN];
#pragma unroll
    for (int n = 0; n < TN; n++) wmma::fill_fragment(c[n], 0.0f);

    for (int k0 = 0; k0 < K; k0 += KC) {
        if (GATHER) {
            // 128 rows x 8 float4 (= 32 floats per row)
            for (int i = tid; i < MTILE * 8; i += 256) {
                int r = i >> 3, seg = i & 7;
                int atom = sidx[r];
                float4 v = make_float4(0.f, 0.f, 0.f, 0.f);
                if (atom >= 0)
                    v = *reinterpret_cast<const float4*>(Ag + (size_t)atom * AEVD + k0 + seg * 4);
                *reinterpret_cast<float4*>(sA + r * LDA_CH + seg * 4) = v;
            }
        }
        // Stage weight chunk: KC x N (N multiple of 4)
        for (int i = tid * 4; i < KC * N; i += 256 * 4) {
            int r = i / N, j = i - r * N;
            float4 v = *reinterpret_cast<const float4*>(Wg + (size_t)(k0 + r) * N + j);
            *reinterpret_cast<float4*>(sW + r * LW + j) = v;
        }
        __syncthreads();

        const float* Abase = GATHER ? sA : (Asm + k0);
        const int    la    = GATHER ? LDA_CH : lda;
#pragma unroll
        for (int kk = 0; kk < KC; kk += 8) {
            wmma::fragment<wmma::matrix_a, 16, 16, 8, wmma::precision::tf32, wmma::row_major> a;
            wmma::load_matrix_sync(a, Abase + warp * 16 * la + kk, la);
#pragma unroll
            for (int t = 0; t < a.num_elements; t++) a.x[t] = wmma::__float_to_tf32(a.x[t]);
#pragma unroll
            for (int n = 0; n < TN; n++) {
                wmma::fragment<wmma::matrix_b, 16, 16, 8, wmma::precision::tf32, wmma::row_major> b;
                wmma::load_matrix_sync(b, sW + kk * LW + n * 16, LW);
#pragma unroll
                for (int t = 0; t < b.num_elements; t++) b.x[t] = wmma::__float_to_tf32(b.x[t]);
                wmma::mma_sync(c[n], a, b, c[n]);
            }
        }
        __syncthreads();
    }

#pragma unroll
    for (int n = 0; n < TN; n++)
        wmma::store_matrix_sync(Hout + warp * 16 * ldo + n * 16, c[n], ldo, wmma::mem_row_major);
    __syncthreads();

    // bias + celu, elementwise
    for (int i = tid; i < MTILE * N; i += 256) {
        int r = i / N, j = i - r * N;
        float x = Hout[r * ldo + j] + bg[j];
        Hout[r * ldo + j] = celu_f(x);
    }
    __syncthreads();
}

__global__ void __launch_bounds__(256)
ani_kernel(const float* __restrict__ aev,
           const float* __restrict__ W1, const float* __restrict__ b1,
           const float* __restrict__ W2, const float* __restrict__ b2,
           const float* __restrict__ W3, const float* __restrict__ b3,
           const float* __restrict__ W4, const float* __restrict__ b4,
           const int* __restrict__ idx0, const int* __restrict__ idx1,
           const int* __restrict__ idx2, const int* __restrict__ idx3,
           int4 cnts)
{
    extern __shared__ __align__(128) float smem[];
    __shared__ int   sidx[MTILE];
    __shared__ float sred[8];

    float* sA  = smem;
    float* sW  = sA + SZ_A;
    float* sH1 = sW + SZ_W;
    float* sH2 = sH1 + SZ_H1;
    float* sH3 = sH1;   // h1 dead after layer 2 -> reuse for h3

    const int s    = blockIdx.y;
    const int tile = blockIdx.x;
    const int cnt  = (&cnts.x)[s];
    const int flat = s * gridDim.x + tile;
    const int base = tile * MTILE;
    const int tid  = threadIdx.x;

    if (base >= cnt) {  // inactive tile (species counts can differ)
        if (tid == 0) g_partials[flat] = 0.0f;
        return;
    }
    const int* idx = (s == 0) ? idx0 : (s == 1) ? idx1 : (s == 2) ? idx2 : idx3;
    if (tid < MTILE) sidx[tid] = (base + tid < cnt) ? idx[base + tid] : -1;
    __syncthreads();

    run_layer<AEVD, H1D, true >(aev, sidx, nullptr, 0,
                                W1 + (size_t)s * AEVD * H1D, b1 + s * H1D,
                                sA, sW, sH1, LDH1);
    run_layer<H1D, H2D, false>(nullptr, nullptr, sH1, LDH1,
                                W2 + (size_t)s * H1D * H2D, b2 + s * H2D,
                                sA, sW, sH2, LDH2);
    run_layer<H2D, H3D, false>(nullptr, nullptr, sH2, LDH2,
                                W3 + (size_t)s * H2D * H3D, b3 + s * H3D,
                                sA, sW, sH3, LDH3);

    // Layer 4: per-atom dot(h3, W4[s]) + b4[s], masked, then deterministic CTA reduce
    const float* W4s = W4 + s * H3D;
    float e = 0.0f;
    if (tid < MTILE) {
        if (base + tid < cnt) {
            float acc = b4[s];
#pragma unroll
            for (int j = 0; j < H3D; j++)
                acc += sH3[tid * LDH3 + j] * __ldg(W4s + j);
            e = acc;
        }
#pragma unroll
        for (int o = 16; o > 0; o >>= 1)
            e += __shfl_down_sync(0xffffffffu, e, o);
        if ((tid & 31) == 0) sred[tid >> 5] = e;
    }
    __syncthreads();
    if (tid == 0)
        g_partials[flat] = sred[0] + sred[1] + sred[2] + sred[3];
}

__global__ void __launch_bounds__(256)
reduce_kernel(int n, float* __restrict__ out)
{
    __shared__ double sd[256];
    double acc = 0.0;
    for (int i = threadIdx.x; i < n; i += 256) acc += (double)g_partials[i];
    sd[threadIdx.x] = acc;
    __syncthreads();
#pragma unroll
    for (int o = 128; o > 0; o >>= 1) {
        if (threadIdx.x < o) sd[threadIdx.x] += sd[threadIdx.x + o];
        __syncthreads();
    }
    if (threadIdx.x == 0) out[0] = (float)sd[0];
}

extern "C" void kernel_launch(void* const* d_in, const int* in_sizes, int n_in,
                              void* d_out, int out_size)
{
    const float* aev = (const float*)d_in[0];
    const float* W1  = (const float*)d_in[1];
    const float* b1  = (const float*)d_in[2];
    const float* W2  = (const float*)d_in[3];
    const float* b2  = (const float*)d_in[4];
    const float* W3  = (const float*)d_in[5];
    const float* b3  = (const float*)d_in[6];
    const float* W4  = (const float*)d_in[7];
    const float* b4  = (const float*)d_in[8];
    const int* idx0  = (const int*)d_in[9];
    const int* idx1  = (const int*)d_in[10];
    const int* idx2  = (const int*)d_in[11];
    const int* idx3  = (const int*)d_in[12];

    int4 cnts;
    cnts.x = in_sizes[9];
    cnts.y = in_sizes[10];
    cnts.z = in_sizes[11];
    cnts.w = in_sizes[12];
    int maxc = cnts.x;
    if (cnts.y > maxc) maxc = cnts.y;
    if (cnts.z > maxc) maxc = cnts.z;
    if (cnts.w > maxc) maxc = cnts.w;
    int tiles = (maxc + MTILE - 1) / MTILE;

    cudaFuncSetAttribute(ani_kernel, cudaFuncAttributeMaxDynamicSharedMemorySize, SMEM_BYTES);

    dim3 grid(tiles, 4);
    ani_kernel<<<grid, 256, SMEM_BYTES>>>(aev, W1, b1, W2, b2, W3, b3, W4, b4,
                                          idx0, idx1, idx2, idx3, cnts);
    reduce_kernel<<<1, 256>>>(tiles * 4, (float*)d_out);
}

// round 6
// speedup vs baseline: 3.0739x; 3.0739x over previous
#include <cuda_runtime.h>
#include <cuda_bf16.h>
#include <cstdint>

// ---------------- problem constants ----------------
constexpr int AEVD = 384;
constexpr int H1D  = 160;
constexpr int H2D  = 128;
constexpr int H3D  = 96;
constexpr int MT   = 128;    // atoms per CTA

// transposed tf32-rounded weights: W1T[4][160][384], W2T[4][128][160], W3T[4][96][128]
__device__ float g_WT[376832];
__device__ float g_partials[4096];
constexpr int W1T_OFF = 0;
constexpr int W2T_OFF = 245760;
constexpr int W3T_OFF = 327680;

// ---------------- SMEM layout (bytes) ----------------
// strides chosen ≡ 16 (mod 128) bytes → 8-row fragment access groups conflict-free,
// and every row 16B-aligned for cp.async.
constexpr int SCH   = 144;                 // staged chunk row stride (36 f)
constexpr int LDH1B = 656;                 // h1 row stride (164 f)
constexpr int LDH2B = 528;                 // h2 row stride (132 f)
constexpr int OFF_H1   = 0;                // 128*656 = 83968
constexpr int OFF_W0   = 83968;            // 160*144 = 23040
constexpr int OFF_W1   = 107008;           // 23040
constexpr int OFF_A0   = 130048;           // 128*144 = 18432
constexpr int OFF_A1   = 148480;           // 18432 (ends 166912)
constexpr int OFF_H2   = OFF_A0;           // overlay: A bufs dead after layer 1 (128*528=67584, ends 197632)
constexpr int OFF_SIDX = 197632;           // 128 int
constexpr int OFF_PD   = 198144;           // 128*2 f
constexpr int OFF_SRED = 199168;           // 8 f
constexpr int SMEM_DYN = 199680;

// ---------------- helpers ----------------
__device__ __forceinline__ uint32_t smem_u32(const void* p) {
    uint32_t a;
    asm("{ .reg .u64 t; cvta.to.shared.u64 t, %1; cvt.u32.u64 %0, t; }" : "=r"(a) : "l"(p));
    return a;
}
__device__ __forceinline__ float to_tf32(float x) {
    float y; asm("cvt.rna.tf32.f32 %0, %1;" : "=f"(y) : "f"(x)); return y;
}
__device__ __forceinline__ uint32_t to_tf32_bits(float x) {
    float y; asm("cvt.rna.tf32.f32 %0, %1;" : "=f"(y) : "f"(x));
    return __float_as_uint(y);
}
__device__ __forceinline__ float celu_f(float x) {
    return x > 0.0f ? x : 0.1f * (expf(x * 10.0f) - 1.0f);
}
__device__ __forceinline__ void cp_async16(uint32_t dst, const void* src, int nbytes) {
    asm volatile("cp.async.cg.shared.global [%0], [%1], 16, %2;"
                 :: "r"(dst), "l"(src), "r"(nbytes) : "memory");
}
__device__ __forceinline__ void cp_commit() {
    asm volatile("cp.async.commit_group;" ::: "memory");
}
__device__ __forceinline__ void cp_wait1() {
    asm volatile("cp.async.wait_group 1;" ::: "memory");
}
__device__ __forceinline__ void cp_wait0() {
    asm volatile("cp.async.wait_group 0;" ::: "memory");
}
__device__ __forceinline__ float lds_f(const char* p) {
    return *reinterpret_cast<const float*>(p);
}
// D += A(16x8, tf32 row) * B(8x8, tf32 col)
__device__ __forceinline__ void mma8(float* d, const uint32_t* a, uint32_t b0, uint32_t b1) {
    asm volatile(
        "mma.sync.aligned.m16n8k8.row.col.f32.tf32.tf32.f32 "
        "{%0,%1,%2,%3}, {%4,%5,%6,%7}, {%8,%9}, {%0,%1,%2,%3};"
        : "+f"(d[0]), "+f"(d[1]), "+f"(d[2]), "+f"(d[3])
        : "r"(a[0]), "r"(a[1]), "r"(a[2]), "r"(a[3]), "r"(b0), "r"(b1));
}

// ---------------- staging (one 32-float K chunk) ----------------
template<int K, bool GATHER>
__device__ __forceinline__ void stage_chunk(
    const float* __restrict__ gA, const int* __restrict__ sidx,
    const float* __restrict__ gWT, int N, int c, char* ab, char* wb, int tid)
{
    const int k0 = c * 32;
    if (GATHER) {
        uint32_t abs_ = smem_u32(ab);
        for (int i = tid; i < 128 * 8; i += 256) {
            int r = i >> 3, s7 = i & 7;
            int atom = sidx[r];
            const float* src = gA + (atom < 0 ? 0 : ((size_t)atom * AEVD + k0 + s7 * 4));
            cp_async16(abs_ + r * SCH + s7 * 16, src, atom < 0 ? 0 : 16);
        }
    }
    uint32_t wbs = smem_u32(wb);
    for (int i = tid; i < N * 8; i += 256) {
        int n = i >> 3, s7 = i & 7;
        cp_async16(wbs + n * SCH + s7 * 16, gWT + (size_t)n * K + k0 + s7 * 4, 16);
    }
    cp_commit();
}

// ---------------- one MLP layer ----------------
// Warp w: m-half mh=w&3 (rows mh*32..mh*32+31 as two m16 tiles), n-half nh=w>>2.
// TN = (N/2)/8 n8-tiles per warp. Accumulators live in registers for the whole layer.
// A fragments are RN-rounded to tf32 in registers (HW mma would truncate RZ ->
// biased error that the 200k-term cancelling sum amplifies; see R4 post-mortem).
template<int K, int N, bool GATHER, bool FINAL>
__device__ __forceinline__ void layer(
    const float* __restrict__ gA, const int* __restrict__ sidx,
    const char* __restrict__ hA, int lda,            // resident A (bytes stride)
    const float* __restrict__ gWT,
    const float* __restrict__ bias, const float* __restrict__ w4,
    char* __restrict__ smem, char* __restrict__ hout, int ldo,
    float* __restrict__ pd)
{
    constexpr int NC = K / 32;
    constexpr int NH = N / 2;
    constexpr int TN = NH / 8;
    const int tid  = threadIdx.x;
    const int lane = tid & 31, w = tid >> 5;
    const int mh = w & 3, nh = w >> 2;
    const int g = lane >> 2, tig = lane & 3;

    float acc[2][TN][4];
#pragma unroll
    for (int mt = 0; mt < 2; mt++)
#pragma unroll
        for (int t = 0; t < TN; t++)
#pragma unroll
            for (int j = 0; j < 4; j++) acc[mt][t][j] = 0.0f;

    char* abufs[2] = { smem + OFF_A0, smem + OFF_A1 };
    char* wbufs[2] = { smem + OFF_W0, smem + OFF_W1 };

    stage_chunk<K, GATHER>(gA, sidx, gWT, N, 0, abufs[0], wbufs[0], tid);

    for (int c = 0; c < NC; c++) {
        if (c + 1 < NC) {
            stage_chunk<K, GATHER>(gA, sidx, gWT, N, c + 1,
                                   abufs[(c + 1) & 1], wbufs[(c + 1) & 1], tid);
            cp_wait1();
        } else {
            cp_wait0();
        }
        __syncthreads();

        const char* ab; int las;
        if (GATHER) { ab = abufs[c & 1]; las = SCH; }
        else        { ab = hA + c * 128; las = lda; }      // +32 floats per chunk
        const char* wb = wbufs[c & 1];

#pragma unroll
        for (int k8 = 0; k8 < 4; k8++) {
            const int kc = k8 * 8;
            uint32_t a[2][4];
#pragma unroll
            for (int mt = 0; mt < 2; mt++) {
                const char* ar = ab + (mh * 32 + mt * 16 + g) * las + (kc + tig) * 4;
                a[mt][0] = to_tf32_bits(lds_f(ar));
                a[mt][1] = to_tf32_bits(lds_f(ar + 8 * las));
                a[mt][2] = to_tf32_bits(lds_f(ar + 16));
                a[mt][3] = to_tf32_bits(lds_f(ar + 8 * las + 16));
            }
#pragma unroll
            for (int t = 0; t < TN; t++) {
                const char* br = wb + (nh * NH + t * 8 + g) * SCH + (kc + tig) * 4;
                uint32_t b0 = __float_as_uint(lds_f(br));   // weights already RN tf32
                uint32_t b1 = __float_as_uint(lds_f(br + 16));
                mma8(acc[0][t], a[0], b0, b1);
                mma8(acc[1][t], a[1], b0, b1);
            }
        }
        __syncthreads();   // protect buf[c&1] before restage at c+2
    }

    // ---- epilogue ----
    if (FINAL) {
#pragma unroll
        for (int mt = 0; mt < 2; mt++) {
            float slo = 0.0f, shi = 0.0f;
#pragma unroll
            for (int t = 0; t < TN; t++) {
                int col = nh * NH + t * 8 + 2 * tig;
                float b0 = __ldg(bias + col), b1 = __ldg(bias + col + 1);
                float w0 = __ldg(w4 + col),   w1 = __ldg(w4 + col + 1);
                slo += celu_f(acc[mt][t][0] + b0) * w0 + celu_f(acc[mt][t][1] + b1) * w1;
                shi += celu_f(acc[mt][t][2] + b0) * w0 + celu_f(acc[mt][t][3] + b1) * w1;
            }
#pragma unroll
            for (int o = 1; o <= 2; o <<= 1) {
                slo += __shfl_xor_sync(0xffffffffu, slo, o);
                shi += __shfl_xor_sync(0xffffffffu, shi, o);
            }
            if (tig == 0) {
                int r = mh * 32 + mt * 16 + g;
                pd[r * 2 + nh]       = slo;
                pd[(r + 8) * 2 + nh] = shi;
            }
        }
    } else {
#pragma unroll
        for (int mt = 0; mt < 2; mt++) {
            int r = mh * 32 + mt * 16 + g;
#pragma unroll
            for (int t = 0; t < TN; t++) {
                int col = nh * NH + t * 8 + 2 * tig;
                float b0 = __ldg(bias + col), b1 = __ldg(bias + col + 1);
                float2 lo = make_float2(celu_f(acc[mt][t][0] + b0), celu_f(acc[mt][t][1] + b1));
                float2 hi = make_float2(celu_f(acc[mt][t][2] + b0), celu_f(acc[mt][t][3] + b1));
                *reinterpret_cast<float2*>(hout + r * ldo + col * 4)       = lo;
                *reinterpret_cast<float2*>(hout + (r + 8) * ldo + col * 4) = hi;
            }
        }
    }
}

// ---------------- main kernel ----------------
__global__ void __launch_bounds__(256, 1)
ani_kernel(const float* __restrict__ aev,
           const float* __restrict__ b1, const float* __restrict__ b2,
           const float* __restrict__ b3,
           const float* __restrict__ W4, const float* __restrict__ b4,
           const int* __restrict__ idx0, const int* __restrict__ idx1,
           const int* __restrict__ idx2, const int* __restrict__ idx3,
           int4 cnts)
{
    extern __shared__ __align__(128) char smem[];

    const int s    = blockIdx.y;
    const int tile = blockIdx.x;
    const int cnt  = (&cnts.x)[s];
    const int flat = s * gridDim.x + tile;
    const int base = tile * MT;
    const int tid  = threadIdx.x;

    if (base >= cnt) { if (tid == 0) g_partials[flat] = 0.0f; return; }

    int*   sidx = (int*)(smem + OFF_SIDX);
    float* pd   = (float*)(smem + OFF_PD);
    float* sred = (float*)(smem + OFF_SRED);

    const int* idx = (s == 0) ? idx0 : (s == 1) ? idx1 : (s == 2) ? idx2 : idx3;
    if (tid < MT) sidx[tid] = (base + tid < cnt) ? idx[base + tid] : -1;
    __syncthreads();

    // layer 1: gather aev [128x384] @ W1 -> h1 [128x160]
    layer<AEVD, H1D, true, false>(aev, sidx, nullptr, 0,
                                  g_WT + W1T_OFF + (size_t)s * H1D * AEVD,
                                  b1 + s * H1D, nullptr,
                                  smem, smem + OFF_H1, LDH1B, nullptr);
    __syncthreads();
    // layer 2: h1 @ W2 -> h2 [128x128]
    layer<H1D, H2D, false, false>(nullptr, nullptr, smem + OFF_H1, LDH1B,
                                  g_WT + W2T_OFF + (size_t)s * H2D * H1D,
                                  b2 + s * H2D, nullptr,
                                  smem, smem + OFF_H2, LDH2B, nullptr);
    __syncthreads();
    // layer 3: h2 @ W3 -> celu -> fused dot with W4 -> pd
    layer<H2D, H3D, false, true>(nullptr, nullptr, smem + OFF_H2, LDH2B,
                                 g_WT + W3T_OFF + (size_t)s * H3D * H2D,
                                 b3 + s * H3D, W4 + s * H3D,
                                 smem, nullptr, 0, pd);
    __syncthreads();

    // combine halves, mask pads, block reduce
    float e = 0.0f;
    if (tid < MT) {
        if (base + tid < cnt) e = pd[tid * 2] + pd[tid * 2 + 1] + __ldg(b4 + s);
#pragma unroll
        for (int o = 16; o > 0; o >>= 1) e += __shfl_down_sync(0xffffffffu, e, o);
        if ((tid & 31) == 0) sred[tid >> 5] = e;
    }
    __syncthreads();
    if (tid == 0) g_partials[flat] = sred[0] + sred[1] + sred[2] + sred[3];
}

// ---------------- weight transpose + tf32 RN round (once per launch) -------
__global__ void __launch_bounds__(256)
prep_kernel(const float* __restrict__ W1, const float* __restrict__ W2,
            const float* __restrict__ W3)
{
    int i = blockIdx.x * 256 + threadIdx.x;
    if (i < 4 * AEVD * H1D) {
        int sp = i / (AEVD * H1D), r = i % (AEVD * H1D);
        int k = r / H1D, n = r % H1D;
        g_WT[W1T_OFF + sp * H1D * AEVD + n * AEVD + k] = to_tf32(W1[i]);
    }
    if (i < 4 * H1D * H2D) {
        int sp = i / (H1D * H2D), r = i % (H1D * H2D);
        int k = r / H2D, n = r % H2D;
        g_WT[W2T_OFF + sp * H2D * H1D + n * H1D + k] = to_tf32(W2[i]);
    }
    if (i < 4 * H2D * H3D) {
        int sp = i / (H2D * H3D), r = i % (H2D * H3D);
        int k = r / H3D, n = r % H3D;
        g_WT[W3T_OFF + sp * H3D * H2D + n * H2D + k] = to_tf32(W3[i]);
    }
}

__global__ void __launch_bounds__(256)
reduce_kernel(int n, float* __restrict__ out)
{
    __shared__ double sd[256];
    double acc = 0.0;
    for (int i = threadIdx.x; i < n; i += 256) acc += (double)g_partials[i];
    sd[threadIdx.x] = acc;
    __syncthreads();
#pragma unroll
    for (int o = 128; o > 0; o >>= 1) {
        if (threadIdx.x < o) sd[threadIdx.x] += sd[threadIdx.x + o];
        __syncthreads();
    }
    if (threadIdx.x == 0) out[0] = (float)sd[0];
}

extern "C" void kernel_launch(void* const* d_in, const int* in_sizes, int n_in,
                              void* d_out, int out_size)
{
    const float* aev = (const float*)d_in[0];
    const float* W1  = (const float*)d_in[1];
    const float* b1  = (const float*)d_in[2];
    const float* W2  = (const float*)d_in[3];
    const float* b2  = (const float*)d_in[4];
    const float* W3  = (const float*)d_in[5];
    const float* b3  = (const float*)d_in[6];
    const float* W4  = (const float*)d_in[7];
    const float* b4  = (const float*)d_in[8];
    const int* idx0  = (const int*)d_in[9];
    const int* idx1  = (const int*)d_in[10];
    const int* idx2  = (const int*)d_in[11];
    const int* idx3  = (const int*)d_in[12];

    int4 cnts;
    cnts.x = in_sizes[9];  cnts.y = in_sizes[10];
    cnts.z = in_sizes[11]; cnts.w = in_sizes[12];
    int maxc = cnts.x;
    if (cnts.y > maxc) maxc = cnts.y;
    if (cnts.z > maxc) maxc = cnts.z;
    if (cnts.w > maxc) maxc = cnts.w;
    int tiles = (maxc + MT - 1) / MT;

    prep_kernel<<<(4 * AEVD * H1D + 255) / 256, 256>>>(W1, W2, W3);

    cudaFuncSetAttribute(ani_kernel, cudaFuncAttributeMaxDynamicSharedMemorySize, SMEM_DYN);
    dim3 grid(tiles, 4);
    ani_kernel<<<grid, 256, SMEM_DYN>>>(aev, b1, b2, b3, W4, b4,
                                        idx0, idx1, idx2, idx3, cnts);
    reduce_kernel<<<1, 256>>>(tiles * 4, (float*)d_out);
}

// round 8
// speedup vs baseline: 5.9899x; 1.9486x over previous
#include <cuda_runtime.h>
#include <cuda_fp16.h>
#include <cstdint>

// ---------------- problem constants ----------------
constexpr int AEVD = 384;
constexpr int H1D  = 160;
constexpr int H2D  = 128;
constexpr int H3D  = 96;
constexpr int MT   = 128;    // atoms per CTA

// transposed RN-fp16 weights: W1T[4][160][384], W2T[4][128][160], W3T[4][96][128]
__device__ __half g_WTh[376832];
__device__ float g_partials[4096];
constexpr int W1T_OFF = 0;
constexpr int W2T_OFF = 245760;
constexpr int W3T_OFF = 327680;

// ---------------- SMEM layout (bytes) ----------------
// all strides ≡ 16 or 80 (mod 128) → conflict-free 8-row quad access groups
constexpr int SCH   = 144;     // L1 A chunk row stride (32 fp32 + pad)
constexpr int WCH   = 80;      // W chunk row stride (32 fp16 + pad)
constexpr int LD1B  = 336;     // h1 row stride bytes (168 fp16)
constexpr int LD2B  = 272;     // h2 row stride bytes (136 fp16)
constexpr int OFF_H1   = 0;        // 128*336 = 43008
constexpr int OFF_W0   = 43008;    // 160*80 = 12800
constexpr int OFF_W1   = 55808;    // end 68608
constexpr int OFF_A0   = 68608;    // 128*144 = 18432
constexpr int OFF_A1   = 87040;    // end 105472
constexpr int OFF_H2   = OFF_A0;   // overlay: A bufs dead after L1 (128*272=34816, end 103424)
constexpr int OFF_SIDX = 105472;   // 128 int
constexpr int OFF_PD   = 105984;   // 256 f
constexpr int OFF_SRED = 107008;   // 8 f
constexpr int SMEM_DYN = 107136;   // x2 CTAs = 214272 < 228KB/SM

// ---------------- helpers ----------------
__device__ __forceinline__ uint32_t smem_u32(const void* p) {
    uint32_t a;
    asm("{ .reg .u64 t; cvta.to.shared.u64 t, %1; cvt.u32.u64 %0, t; }" : "=r"(a) : "l"(p));
    return a;
}
__device__ __forceinline__ float celu_f(float x) {
    return x > 0.0f ? x : 0.1f * (expf(x * 10.0f) - 1.0f);
}
// pack (lo, hi) -> f16x2, RN (first asm source = high half)
__device__ __forceinline__ uint32_t pack_f16(float lo, float hi) {
    uint32_t r;
    asm("cvt.rn.f16x2.f32 %0, %1, %2;" : "=r"(r) : "f"(hi), "f"(lo));
    return r;
}
__device__ __forceinline__ void cp_async16(uint32_t dst, const void* src, int nbytes) {
    asm volatile("cp.async.cg.shared.global [%0], [%1], 16, %2;"
                 :: "r"(dst), "l"(src), "r"(nbytes) : "memory");
}
__device__ __forceinline__ void cp_commit() { asm volatile("cp.async.commit_group;" ::: "memory"); }
__device__ __forceinline__ void cp_wait1()  { asm volatile("cp.async.wait_group 1;" ::: "memory"); }
__device__ __forceinline__ void cp_wait0()  { asm volatile("cp.async.wait_group 0;" ::: "memory"); }

// D += A(16x16 fp16 row) * B(16x8 fp16 col), fp32 accum
__device__ __forceinline__ void mma16(float* d, const uint32_t* a, uint32_t b0, uint32_t b1) {
    asm volatile(
        "mma.sync.aligned.m16n8k16.row.col.f32.f16.f16.f32 "
        "{%0,%1,%2,%3}, {%4,%5,%6,%7}, {%8,%9}, {%0,%1,%2,%3};"
        : "+f"(d[0]), "+f"(d[1]), "+f"(d[2]), "+f"(d[3])
        : "r"(a[0]), "r"(a[1]), "r"(a[2]), "r"(a[3]), "r"(b0), "r"(b1));
}

// ---------------- staging of one 32-k chunk ----------------
template<int K, bool GATHER>
__device__ __forceinline__ void stage_chunk(
    const float* __restrict__ gA, const int* __restrict__ sidx,
    const __half* __restrict__ gWT, int N, int c,
    char* ab, char* wb, int tid)
{
    const int k0 = c * 32;
    if (GATHER) {
        uint32_t abs_ = smem_u32(ab);
        for (int i = tid; i < 128 * 8; i += 256) {
            int r = i >> 3, s7 = i & 7;
            int atom = sidx[r];
            const float* src = gA + (atom < 0 ? 0 : ((size_t)atom * AEVD + k0 + s7 * 4));
            cp_async16(abs_ + r * SCH + s7 * 16, src, atom < 0 ? 0 : 16);
        }
    }
    uint32_t wbs = smem_u32(wb);
    for (int i = tid; i < N * 4; i += 256) {
        int n = i >> 2, s3 = i & 3;
        cp_async16(wbs + n * WCH + s3 * 16, gWT + (size_t)n * K + k0 + s3 * 8, 16);
    }
    cp_commit();
}

// ---------------- one MLP layer (fp16 mma, fp32 accum) ----------------
// Warp w: m-quarter mh=w&3 (2 m16 tiles), n-half nh=w>>2 (TN = N/16 n8-tiles).
template<int K, int N, bool GATHER, bool FINAL>
__device__ __forceinline__ void layer(
    const float* __restrict__ gA, const int* __restrict__ sidx,
    const char* __restrict__ hA, int lda,            // resident fp16 A (byte stride)
    const __half* __restrict__ gWT,
    const float* __restrict__ bias, const float* __restrict__ w4,
    char* __restrict__ smem, char* __restrict__ hout, int ldo,
    float* __restrict__ pd)
{
    constexpr int NC = K / 32;
    constexpr int NH = N / 2;
    constexpr int TN = NH / 8;
    const int tid  = threadIdx.x;
    const int lane = tid & 31, w = tid >> 5;
    const int mh = w & 3, nh = w >> 2;
    const int g = lane >> 2, tig = lane & 3;

    float acc[2][TN][4];
#pragma unroll
    for (int mt = 0; mt < 2; mt++)
#pragma unroll
        for (int t = 0; t < TN; t++)
#pragma unroll
            for (int j = 0; j < 4; j++) acc[mt][t][j] = 0.0f;

    char* abufs[2] = { smem + OFF_A0, smem + OFF_A1 };
    char* wbufs[2] = { smem + OFF_W0, smem + OFF_W1 };

    stage_chunk<K, GATHER>(gA, sidx, gWT, N, 0, abufs[0], wbufs[0], tid);

    for (int c = 0; c < NC; c++) {
        if (c + 1 < NC) {
            stage_chunk<K, GATHER>(gA, sidx, gWT, N, c + 1,
                                   abufs[(c + 1) & 1], wbufs[(c + 1) & 1], tid);
            cp_wait1();
        } else {
            cp_wait0();
        }
        __syncthreads();

        const char* wb = wbufs[c & 1];
        const char* ab = GATHER ? abufs[c & 1] : (hA + c * 64);  // 32 fp16 = 64B/chunk

#pragma unroll
        for (int h = 0; h < 2; h++) {        // two k16 halves per 32-chunk
            const int kc = h * 16;
            uint32_t a[2][4];
#pragma unroll
            for (int mt = 0; mt < 2; mt++) {
                const int r0 = mh * 32 + mt * 16 + g;
                if (GATHER) {
                    const char* ar = ab + r0 * SCH + (kc + 2 * tig) * 4;
                    float2 p0 = *reinterpret_cast<const float2*>(ar);
                    float2 p1 = *reinterpret_cast<const float2*>(ar + 8 * SCH);
                    float2 p2 = *reinterpret_cast<const float2*>(ar + 32);
                    float2 p3 = *reinterpret_cast<const float2*>(ar + 8 * SCH + 32);
                    a[mt][0] = pack_f16(p0.x, p0.y);
                    a[mt][1] = pack_f16(p1.x, p1.y);
                    a[mt][2] = pack_f16(p2.x, p2.y);
                    a[mt][3] = pack_f16(p3.x, p3.y);
                } else {
                    const char* ar = hA + r0 * lda + c * 64 + (kc + 2 * tig) * 2;
                    a[mt][0] = *reinterpret_cast<const uint32_t*>(ar);
                    a[mt][1] = *reinterpret_cast<const uint32_t*>(ar + 8 * lda);
                    a[mt][2] = *reinterpret_cast<const uint32_t*>(ar + 16);
                    a[mt][3] = *reinterpret_cast<const uint32_t*>(ar + 8 * lda + 16);
                }
            }
#pragma unroll
            for (int t = 0; t < TN; t++) {
                const char* br = wb + (nh * NH + t * 8 + g) * WCH + kc * 2 + tig * 4;
                uint32_t b0 = *reinterpret_cast<const uint32_t*>(br);
                uint32_t b1 = *reinterpret_cast<const uint32_t*>(br + 16);
                mma16(acc[0][t], a[0], b0, b1);
                mma16(acc[1][t], a[1], b0, b1);
            }
        }
        __syncthreads();   // protect buf c&1 before restage at c+2
    }

    // ---- epilogue ----
    if (FINAL) {
#pragma unroll
        for (int mt = 0; mt < 2; mt++) {
            float slo = 0.0f, shi = 0.0f;
#pragma unroll
            for (int t = 0; t < TN; t++) {
                int col = nh * NH + t * 8 + 2 * tig;
                float b0 = __ldg(bias + col), b1 = __ldg(bias + col + 1);
                float w0 = __ldg(w4 + col),   w1 = __ldg(w4 + col + 1);
                slo += celu_f(acc[mt][t][0] + b0) * w0 + celu_f(acc[mt][t][1] + b1) * w1;
                shi += celu_f(acc[mt][t][2] + b0) * w0 + celu_f(acc[mt][t][3] + b1) * w1;
            }
#pragma unroll
            for (int o = 1; o <= 2; o <<= 1) {
                slo += __shfl_xor_sync(0xffffffffu, slo, o);
                shi += __shfl_xor_sync(0xffffffffu, shi, o);
            }
            if (tig == 0) {
                int r = mh * 32 + mt * 16 + g;
                pd[r * 2 + nh]       = slo;
                pd[(r + 8) * 2 + nh] = shi;
            }
        }
    } else {
#pragma unroll
        for (int mt = 0; mt < 2; mt++) {
            int r = mh * 32 + mt * 16 + g;
#pragma unroll
            for (int t = 0; t < TN; t++) {
                int col = nh * NH + t * 8 + 2 * tig;
                float b0 = __ldg(bias + col), b1 = __ldg(bias + col + 1);
                uint32_t lo = pack_f16(celu_f(acc[mt][t][0] + b0), celu_f(acc[mt][t][1] + b1));
                uint32_t hi = pack_f16(celu_f(acc[mt][t][2] + b0), celu_f(acc[mt][t][3] + b1));
                *reinterpret_cast<uint32_t*>(hout + r * ldo + col * 2)       = lo;
                *reinterpret_cast<uint32_t*>(hout + (r + 8) * ldo + col * 2) = hi;
            }
        }
    }
}

// ---------------- main kernel ----------------
__global__ void __launch_bounds__(256, 2)
ani_kernel(const float* __restrict__ aev,
           const float* __restrict__ b1, const float* __restrict__ b2,
           const float* __restrict__ b3,
           const float* __restrict__ W4, const float* __restrict__ b4,
           const int* __restrict__ idx0, const int* __restrict__ idx1,
           const int* __restrict__ idx2, const int* __restrict__ idx3,
           int4 cnts)
{
    extern __shared__ __align__(128) char smem[];

    const int s    = blockIdx.y;
    const int tile = blockIdx.x;
    const int cnt  = (&cnts.x)[s];
    const int flat = s * gridDim.x + tile;
    const int base = tile * MT;
    const int tid  = threadIdx.x;

    if (base >= cnt) { if (tid == 0) g_partials[flat] = 0.0f; return; }

    int*   sidx = (int*)(smem + OFF_SIDX);
    float* pd   = (float*)(smem + OFF_PD);
    float* sred = (float*)(smem + OFF_SRED);

    const int* idx = (s == 0) ? idx0 : (s == 1) ? idx1 : (s == 2) ? idx2 : idx3;
    if (tid < MT) sidx[tid] = (base + tid < cnt) ? idx[base + tid] : -1;
    __syncthreads();

    // layer 1: gather aev [128x384] @ W1 -> h1 fp16 [128x160]
    layer<AEVD, H1D, true, false>(aev, sidx, nullptr, 0,
                                  g_WTh + W1T_OFF + (size_t)s * H1D * AEVD,
                                  b1 + s * H1D, nullptr,
                                  smem, smem + OFF_H1, LD1B, nullptr);
    __syncthreads();
    // layer 2: h1 @ W2 -> h2 fp16 [128x128]
    layer<H1D, H2D, false, false>(nullptr, nullptr, smem + OFF_H1, LD1B,
                                  g_WTh + W2T_OFF + (size_t)s * H2D * H1D,
                                  b2 + s * H2D, nullptr,
                                  smem, smem + OFF_H2, LD2B, nullptr);
    __syncthreads();
    // layer 3: h2 @ W3 -> celu -> fused dot W4 -> pd
    layer<H2D, H3D, false, true>(nullptr, nullptr, smem + OFF_H2, LD2B,
                                 g_WTh + W3T_OFF + (size_t)s * H3D * H2D,
                                 b3 + s * H3D, W4 + s * H3D,
                                 smem, nullptr, 0, pd);
    __syncthreads();

    // combine halves, mask pads, block reduce
    float e = 0.0f;
    if (tid < MT) {
        if (base + tid < cnt) e = pd[tid * 2] + pd[tid * 2 + 1] + __ldg(b4 + s);
#pragma unroll
        for (int o = 16; o > 0; o >>= 1) e += __shfl_down_sync(0xffffffffu, e, o);
        if ((tid & 31) == 0) sred[tid >> 5] = e;
    }
    __syncthreads();
    if (tid == 0) g_partials[flat] = sred[0] + sred[1] + sred[2] + sred[3];
}

// ---------------- weight transpose + RN fp16 (once per launch) ------------
__global__ void __launch_bounds__(256)
prep_kernel(const float* __restrict__ W1, const float* __restrict__ W2,
            const float* __restrict__ W3)
{
    int i = blockIdx.x * 256 + threadIdx.x;
    if (i < 4 * AEVD * H1D) {
        int sp = i / (AEVD * H1D), r = i % (AEVD * H1D);
        int k = r / H1D, n = r % H1D;
        g_WTh[W1T_OFF + sp * H1D * AEVD + n * AEVD + k] = __float2half_rn(W1[i]);
    }
    if (i < 4 * H1D * H2D) {
        int sp = i / (H1D * H2D), r = i % (H1D * H2D);
        int k = r / H2D, n = r % H2D;
        g_WTh[W2T_OFF + sp * H2D * H1D + n * H1D + k] = __float2half_rn(W2[i]);
    }
    if (i < 4 * H2D * H3D) {
        int sp = i / (H2D * H3D), r = i % (H2D * H3D);
        int k = r / H3D, n = r % H3D;
        g_WTh[W3T_OFF + sp * H3D * H2D + n * H2D + k] = __float2half_rn(W3[i]);
    }
}

__global__ void __launch_bounds__(256)
reduce_kernel(int n, float* __restrict__ out)
{
    __shared__ double sd[256];
    double acc = 0.0;
    for (int i = threadIdx.x; i < n; i += 256) acc += (double)g_partials[i];
    sd[threadIdx.x] = acc;
    __syncthreads();
#pragma unroll
    for (int o = 128; o > 0; o >>= 1) {
        if (threadIdx.x < o) sd[threadIdx.x] += sd[threadIdx.x + o];
        __syncthreads();
    }
    if (threadIdx.x == 0) out[0] = (float)sd[0];
}

extern "C" void kernel_launch(void* const* d_in, const int* in_sizes, int n_in,
                              void* d_out, int out_size)
{
    const float* aev = (const float*)d_in[0];
    const float* W1  = (const float*)d_in[1];
    const float* b1  = (const float*)d_in[2];
    const float* W2  = (const float*)d_in[3];
    const float* b2  = (const float*)d_in[4];
    const float* W3  = (const float*)d_in[5];
    const float* b3  = (const float*)d_in[6];
    const float* W4  = (const float*)d_in[7];
    const float* b4  = (const float*)d_in[8];
    const int* idx0  = (const int*)d_in[9];
    const int* idx1  = (const int*)d_in[10];
    const int* idx2  = (const int*)d_in[11];
    const int* idx3  = (const int*)d_in[12];

    int4 cnts;
    cnts.x = in_sizes[9];  cnts.y = in_sizes[10];
    cnts.z = in_sizes[11]; cnts.w = in_sizes[12];
    int maxc = cnts.x;
    if (cnts.y > maxc) maxc = cnts.y;
    if (cnts.z > maxc) maxc = cnts.z;
    if (cnts.w > maxc) maxc = cnts.w;
    int tiles = (maxc + MT - 1) / MT;

    prep_kernel<<<(4 * AEVD * H1D + 255) / 256, 256>>>(W1, W2, W3);

    cudaFuncSetAttribute(ani_kernel, cudaFuncAttributeMaxDynamicSharedMemorySize, SMEM_DYN);
    dim3 grid(tiles, 4);
    ani_kernel<<<grid, 256, SMEM_DYN>>>(aev, b1, b2, b3, W4, b4,
                                        idx0, idx1, idx2, idx3, cnts);
    reduce_kernel<<<1, 256>>>(tiles * 4, (float*)d_out);
}

// round 10
// speedup vs baseline: 6.5040x; 1.0858x over previous
#include <cuda_runtime.h>
#include <cuda_fp16.h>
#include <cstdint>

// ---------------- problem constants ----------------
constexpr int AEVD = 384;
constexpr int H1D  = 160;
constexpr int H2D  = 128;
constexpr int H3D  = 96;
constexpr int MT   = 128;    // atoms per CTA

// transposed RN-fp16 weights: W1T[4][160][384], W2T[4][128][160], W3T[4][96][128]
__device__ __half g_WTh[376832];
__device__ float g_partials[4096];
__device__ unsigned int g_ticket;   // zero-init; reset by last CTA each launch
constexpr int W1T_OFF = 0;
constexpr int W2T_OFF = 245760;
constexpr int W3T_OFF = 327680;

// ---------------- SMEM layout (bytes) ----------------
// all strides ≡ 16 or 80 (mod 128) → conflict-free 8-row access groups (LDS + LDSM)
constexpr int SCH   = 144;     // L1 A chunk row stride (32 fp32 + pad)
constexpr int WCH   = 80;      // W chunk row stride (32 fp16 + pad)
constexpr int LD1B  = 336;     // h1 row stride bytes (168 fp16)
constexpr int LD2B  = 272;     // h2 row stride bytes (136 fp16)
constexpr int OFF_H1   = 0;        // 128*336 = 43008
constexpr int OFF_W0   = 43008;    // 160*80 = 12800
constexpr int OFF_W1   = 55808;    // end 68608
constexpr int OFF_A0   = 68608;    // 128*144 = 18432
constexpr int OFF_A1   = 87040;    // end 105472
constexpr int OFF_H2   = OFF_A0;   // overlay: A bufs dead after L1 (128*272=34816, end 103424)
constexpr int OFF_SIDX = 105472;   // 128 int
constexpr int OFF_PD   = 105984;   // 256 f
constexpr int OFF_SRED = 107008;   // 8 f
constexpr int SMEM_DYN = 107136;   // x2 CTAs = 214272 < 228KB/SM

// ---------------- helpers ----------------
__device__ __forceinline__ uint32_t smem_u32(const void* p) {
    uint32_t a;
    asm("{ .reg .u64 t; cvta.to.shared.u64 t, %1; cvt.u32.u64 %0, t; }" : "=r"(a) : "l"(p));
    return a;
}
__device__ __forceinline__ float celu_f(float x) {
    return x > 0.0f ? x : 0.1f * (expf(x * 10.0f) - 1.0f);
}
// pack (lo, hi) -> f16x2, RN (first asm source = high half)
__device__ __forceinline__ uint32_t pack_f16(float lo, float hi) {
    uint32_t r;
    asm("cvt.rn.f16x2.f32 %0, %1, %2;" : "=r"(r) : "f"(hi), "f"(lo));
    return r;
}
__device__ __forceinline__ void cp_async16(uint32_t dst, const void* src, int nbytes) {
    asm volatile("cp.async.cg.shared.global [%0], [%1], 16, %2;"
                 :: "r"(dst), "l"(src), "r"(nbytes) : "memory");
}
__device__ __forceinline__ void cp_commit() { asm volatile("cp.async.commit_group;" ::: "memory"); }
__device__ __forceinline__ void cp_wait1()  { asm volatile("cp.async.wait_group 1;" ::: "memory"); }
__device__ __forceinline__ void cp_wait0()  { asm volatile("cp.async.wait_group 0;" ::: "memory"); }

__device__ __forceinline__ void ldsm_x4(uint32_t& r0, uint32_t& r1, uint32_t& r2, uint32_t& r3,
                                        uint32_t addr) {
    asm volatile("ldmatrix.sync.aligned.m8n8.x4.shared.b16 {%0,%1,%2,%3}, [%4];"
                 : "=r"(r0), "=r"(r1), "=r"(r2), "=r"(r3) : "r"(addr));
}

// D += A(16x16 fp16 row) * B(16x8 fp16 col), fp32 accum
__device__ __forceinline__ void mma16(float* d, const uint32_t* a, uint32_t b0, uint32_t b1) {
    asm volatile(
        "mma.sync.aligned.m16n8k16.row.col.f32.f16.f16.f32 "
        "{%0,%1,%2,%3}, {%4,%5,%6,%7}, {%8,%9}, {%0,%1,%2,%3};"
        : "+f"(d[0]), "+f"(d[1]), "+f"(d[2]), "+f"(d[3])
        : "r"(a[0]), "r"(a[1]), "r"(a[2]), "r"(a[3]), "r"(b0), "r"(b1));
}

// ---------------- staging of one 32-k chunk ----------------
template<int K, bool GATHER>
__device__ __forceinline__ void stage_chunk(
    const float* __restrict__ gA, const int* __restrict__ sidx,
    const __half* __restrict__ gWT, int N, int c,
    char* ab, char* wb, int tid)
{
    const int k0 = c * 32;
    if (GATHER) {
        uint32_t abs_ = smem_u32(ab);
        for (int i = tid; i < 128 * 8; i += 256) {
            int r = i >> 3, s7 = i & 7;
            int atom = sidx[r];
            const float* src = gA + (atom < 0 ? 0 : ((size_t)atom * AEVD + k0 + s7 * 4));
            cp_async16(abs_ + r * SCH + s7 * 16, src, atom < 0 ? 0 : 16);
        }
    }
    uint32_t wbs = smem_u32(wb);
    for (int i = tid; i < N * 4; i += 256) {
        int n = i >> 2, s3 = i & 3;
        cp_async16(wbs + n * WCH + s3 * 16, gWT + (size_t)n * K + k0 + s3 * 8, 16);
    }
    cp_commit();
}

// ---------------- one MLP layer (fp16 mma, fp32 accum, ldmatrix feeds) -----
// Warp w: m-quarter mh=w&3 (2 m16 tiles), n-half nh=w>>2 (TN = N/16 n8-tiles).
template<int K, int N, bool GATHER, bool FINAL>
__device__ __forceinline__ void layer(
    const float* __restrict__ gA, const int* __restrict__ sidx,
    const char* __restrict__ hA, int lda,            // resident fp16 A (byte stride)
    const __half* __restrict__ gWT,
    const float* __restrict__ bias, const float* __restrict__ w4,
    char* __restrict__ smem, char* __restrict__ hout, int ldo,
    float* __restrict__ pd)
{
    constexpr int NC = K / 32;
    constexpr int NH = N / 2;
    constexpr int TN = NH / 8;       // 10, 8, 6
    constexpr int TB = TN / 2;       // 5, 4, 3
    const int tid  = threadIdx.x;
    const int lane = tid & 31, w = tid >> 5;
    const int mh = w & 3, nh = w >> 2;
    const int g = lane >> 2, tig = lane & 3;
    const int lrow = lane & 7, lsub = lane >> 3;

    // ldmatrix lane address offsets
    // B: m0=n(+0..7) k-lo, m1=k-hi, m2=n(+8..15) k-lo, m3=k-hi
    const uint32_t b_lane = (uint32_t)((nh * NH + lrow + (lane >> 4) * 8) * WCH
                                       + ((lane >> 3) & 1) * 16);
    // resident A: m0=rows+0..7 k-lo, m1=rows+8..15 k-lo, m2=rows+0..7 k-hi, m3=k-hi
    uint32_t a_lane[2];
    if (!GATHER) {
        const uint32_t hA_u = smem_u32(hA);
#pragma unroll
        for (int mt = 0; mt < 2; mt++)
            a_lane[mt] = hA_u + (uint32_t)((mh * 32 + mt * 16 + lrow + (lsub & 1) * 8) * lda
                                           + (lsub >> 1) * 16);
    }

    float acc[2][TN][4];
#pragma unroll
    for (int mt = 0; mt < 2; mt++)
#pragma unroll
        for (int t = 0; t < TN; t++)
#pragma unroll
            for (int j = 0; j < 4; j++) acc[mt][t][j] = 0.0f;

    char* abufs[2] = { smem + OFF_A0, smem + OFF_A1 };
    char* wbufs[2] = { smem + OFF_W0, smem + OFF_W1 };

    stage_chunk<K, GATHER>(gA, sidx, gWT, N, 0, abufs[0], wbufs[0], tid);

    for (int c = 0; c < NC; c++) {
        if (c + 1 < NC) {
            stage_chunk<K, GATHER>(gA, sidx, gWT, N, c + 1,
                                   abufs[(c + 1) & 1], wbufs[(c + 1) & 1], tid);
            cp_wait1();
        } else {
            cp_wait0();
        }
        __syncthreads();

        const uint32_t wb_u = smem_u32(wbufs[c & 1]) + b_lane;
        const char* ab = abufs[c & 1];

#pragma unroll
        for (int h = 0; h < 2; h++) {        // two k16 halves per 32-chunk
            uint32_t a[2][4];
            if (GATHER) {
                const int kc = h * 16;
#pragma unroll
                for (int mt = 0; mt < 2; mt++) {
                    const int r0 = mh * 32 + mt * 16 + g;
                    const char* ar = ab + r0 * SCH + (kc + 2 * tig) * 4;
                    float2 p0 = *reinterpret_cast<const float2*>(ar);
                    float2 p1 = *reinterpret_cast<const float2*>(ar + 8 * SCH);
                    float2 p2 = *reinterpret_cast<const float2*>(ar + 32);
                    float2 p3 = *reinterpret_cast<const float2*>(ar + 8 * SCH + 32);
                    a[mt][0] = pack_f16(p0.x, p0.y);
                    a[mt][1] = pack_f16(p1.x, p1.y);
                    a[mt][2] = pack_f16(p2.x, p2.y);
                    a[mt][3] = pack_f16(p3.x, p3.y);
                }
            } else {
#pragma unroll
                for (int mt = 0; mt < 2; mt++)
                    ldsm_x4(a[mt][0], a[mt][1], a[mt][2], a[mt][3],
                            a_lane[mt] + c * 64 + h * 32);
            }
#pragma unroll
            for (int tb = 0; tb < TB; tb++) {
                uint32_t b0, b1, b2, b3;
                ldsm_x4(b0, b1, b2, b3, wb_u + tb * (16 * WCH) + h * 32);
                mma16(acc[0][2 * tb],     a[0], b0, b1);
                mma16(acc[1][2 * tb],     a[1], b0, b1);
                mma16(acc[0][2 * tb + 1], a[0], b2, b3);
                mma16(acc[1][2 * tb + 1], a[1], b2, b3);
            }
        }
        __syncthreads();   // protect buf c&1 before restage at c+2
    }

    // ---- epilogue ----
    if (FINAL) {
#pragma unroll
        for (int mt = 0; mt < 2; mt++) {
            float slo = 0.0f, shi = 0.0f;
#pragma unroll
            for (int t = 0; t < TN; t++) {
                int col = nh * NH + t * 8 + 2 * tig;
                float b0 = __ldg(bias + col), b1 = __ldg(bias + col + 1);
                float w0 = __ldg(w4 + col),   w1 = __ldg(w4 + col + 1);
                slo += celu_f(acc[mt][t][0] + b0) * w0 + celu_f(acc[mt][t][1] + b1) * w1;
                shi += celu_f(acc[mt][t][2] + b0) * w0 + celu_f(acc[mt][t][3] + b1) * w1;
            }
#pragma unroll
            for (int o = 1; o <= 2; o <<= 1) {
                slo += __shfl_xor_sync(0xffffffffu, slo, o);
                shi += __shfl_xor_sync(0xffffffffu, shi, o);
            }
            if (tig == 0) {
                int r = mh * 32 + mt * 16 + g;
                pd[r * 2 + nh]       = slo;
                pd[(r + 8) * 2 + nh] = shi;
            }
        }
    } else {
#pragma unroll
        for (int mt = 0; mt < 2; mt++) {
            int r = mh * 32 + mt * 16 + g;
#pragma unroll
            for (int t = 0; t < TN; t++) {
                int col = nh * NH + t * 8 + 2 * tig;
                float b0 = __ldg(bias + col), b1 = __ldg(bias + col + 1);
                uint32_t lo = pack_f16(celu_f(acc[mt][t][0] + b0), celu_f(acc[mt][t][1] + b1));
                uint32_t hi = pack_f16(celu_f(acc[mt][t][2] + b0), celu_f(acc[mt][t][3] + b1));
                *reinterpret_cast<uint32_t*>(hout + r * ldo + col * 2)       = lo;
                *reinterpret_cast<uint32_t*>(hout + (r + 8) * ldo + col * 2) = hi;
            }
        }
    }
}

// ---------------- main kernel (with fused final reduction) ----------------
__global__ void __launch_bounds__(256, 2)
ani_kernel(const float* __restrict__ aev,
           const float* __restrict__ b1, const float* __restrict__ b2,
           const float* __restrict__ b3,
           const float* __restrict__ W4, const float* __restrict__ b4,
           const int* __restrict__ idx0, const int* __restrict__ idx1,
           const int* __restrict__ idx2, const int* __restrict__ idx3,
           int4 cnts, float* __restrict__ out)
{
    extern __shared__ __align__(128) char smem[];
    __shared__ bool is_last;
    __shared__ double sd[256];

    const int s    = blockIdx.y;
    const int tile = blockIdx.x;
    const int cnt  = (&cnts.x)[s];
    const int flat = s * gridDim.x + tile;
    const int base = tile * MT;
    const int tid  = threadIdx.x;
    const bool active = (base < cnt);

    if (active) {
        int*   sidx = (int*)(smem + OFF_SIDX);
        float* pd   = (float*)(smem + OFF_PD);
        float* sred = (float*)(smem + OFF_SRED);

        const int* idx = (s == 0) ? idx0 : (s == 1) ? idx1 : (s == 2) ? idx2 : idx3;
        if (tid < MT) sidx[tid] = (base + tid < cnt) ? idx[base + tid] : -1;
        __syncthreads();

        // layer 1: gather aev [128x384] @ W1 -> h1 fp16 [128x160]
        layer<AEVD, H1D, true, false>(aev, sidx, nullptr, 0,
                                      g_WTh + W1T_OFF + (size_t)s * H1D * AEVD,
                                      b1 + s * H1D, nullptr,
                                      smem, smem + OFF_H1, LD1B, nullptr);
        __syncthreads();
        // layer 2: h1 @ W2 -> h2 fp16 [128x128]
        layer<H1D, H2D, false, false>(nullptr, nullptr, smem + OFF_H1, LD1B,
                                      g_WTh + W2T_OFF + (size_t)s * H2D * H1D,
                                      b2 + s * H2D, nullptr,
                                      smem, smem + OFF_H2, LD2B, nullptr);
        __syncthreads();
        // layer 3: h2 @ W3 -> celu -> fused dot W4 -> pd
        layer<H2D, H3D, false, true>(nullptr, nullptr, smem + OFF_H2, LD2B,
                                     g_WTh + W3T_OFF + (size_t)s * H3D * H2D,
                                     b3 + s * H3D, W4 + s * H3D,
                                     smem, nullptr, 0, pd);
        __syncthreads();

        // combine halves, mask pads, block reduce
        float e = 0.0f;
        if (tid < MT) {
            if (base + tid < cnt) e = pd[tid * 2] + pd[tid * 2 + 1] + __ldg(b4 + s);
#pragma unroll
            for (int o = 16; o > 0; o >>= 1) e += __shfl_down_sync(0xffffffffu, e, o);
            if ((tid & 31) == 0) sred[tid >> 5] = e;
        }
        __syncthreads();
        if (tid == 0) g_partials[flat] = sred[0] + sred[1] + sred[2] + sred[3];
    } else {
        if (tid == 0) g_partials[flat] = 0.0f;
    }

    // ---- last CTA performs the deterministic global reduction ----
    __threadfence();
    if (tid == 0) {
        unsigned int t = atomicAdd(&g_ticket, 1u);
        is_last = (t == gridDim.x * gridDim.y - 1);
    }
    __syncthreads();
    if (is_last) {
        const int n = gridDim.x * gridDim.y;
        double acc = 0.0;
        for (int i = tid; i < n; i += 256) acc += (double)g_partials[i];
        sd[tid] = acc;
        __syncthreads();
#pragma unroll
        for (int o = 128; o > 0; o >>= 1) {
            if (tid < o) sd[tid] += sd[tid + o];
            __syncthreads();
        }
        if (tid == 0) {
            out[0] = (float)sd[0];
            g_ticket = 0;          // reset for next graph replay
        }
    }
}

// ---------------- weight transpose + RN fp16 (coalesced writes) -----------
__global__ void __launch_bounds__(256)
prep_kernel(const float* __restrict__ W1, const float* __restrict__ W2,
            const float* __restrict__ W3)
{
    int j = blockIdx.x * 256 + threadIdx.x;
    if (j < 4 * H1D * AEVD) {                  // W1T[sp][n][k] <- W1[sp][k][n]
        int sp = j / (H1D * AEVD), r = j % (H1D * AEVD);
        int n = r / AEVD, k = r % AEVD;
        g_WTh[W1T_OFF + j] = __float2half_rn(W1[(size_t)sp * AEVD * H1D + k * H1D + n]);
    }
    if (j < 4 * H2D * H1D) {
        int sp = j / (H2D * H1D), r = j % (H2D * H1D);
        int n = r / H1D, k = r % H1D;
        g_WTh[W2T_OFF + j] = __float2half_rn(W2[(size_t)sp * H1D * H2D + k * H2D + n]);
    }
    if (j < 4 * H3D * H2D) {
        int sp = j / (H3D * H2D), r = j % (H3D * H2D);
        int n = r / H2D, k = r % H2D;
        g_WTh[W3T_OFF + j] = __float2half_rn(W3[(size_t)sp * H2D * H3D + k * H3D + n]);
    }
}

extern "C" void kernel_launch(void* const* d_in, const int* in_sizes, int n_in,
                              void* d_out, int out_size)
{
    const float* aev = (const float*)d_in[0];
    const float* W1  = (const float*)d_in[1];
    const float* b1  = (const float*)d_in[2];
    const float* W2  = (const float*)d_in[3];
    const float* b2  = (const float*)d_in[4];
    const float* W3  = (const float*)d_in[5];
    const float* b3  = (const float*)d_in[6];
    const float* W4  = (const float*)d_in[7];
    const float* b4  = (const float*)d_in[8];
    const int* idx0  = (const int*)d_in[9];
    const int* idx1  = (const int*)d_in[10];
    const int* idx2  = (const int*)d_in[11];
    const int* idx3  = (const int*)d_in[12];

    int4 cnts;
    cnts.x = in_sizes[9];  cnts.y = in_sizes[10];
    cnts.z = in_sizes[11]; cnts.w = in_sizes[12];
    int maxc = cnts.x;
    if (cnts.y > maxc) maxc = cnts.y;
    if (cnts.z > maxc) maxc = cnts.z;
    if (cnts.w > maxc) maxc = cnts.w;
    int tiles = (maxc + MT - 1) / MT;

    prep_kernel<<<(4 * H1D * AEVD + 255) / 256, 256>>>(W1, W2, W3);

    cudaFuncSetAttribute(ani_kernel, cudaFuncAttributeMaxDynamicSharedMemorySize, SMEM_DYN);
    dim3 grid(tiles, 4);
    ani_kernel<<<grid, 256, SMEM_DYN>>>(aev, b1, b2, b3, W4, b4,
                                        idx0, idx1, idx2, idx3, cnts, (float*)d_out);
}